// round 16
// baseline (speedup 1.0000x reference)
#include <cuda_runtime.h>
#include <cuda_fp16.h>
#include <cstdint>

// Problem constants
#define BB 4
#define NQ 16384
#define SS 2048
#define C1 128
#define C2 256
#define HH 256
#define MROWS (BB * NQ)   // 65536
#define SROWS (BB * SS)   // 8192

// ---------------------------------------------------------------------------
// Device scratch
// ---------------------------------------------------------------------------
__device__ float g_Z[SROWS * HH];                 // 8MB, L2-resident
__device__ __half g_h1[(size_t)MROWS * HH];       // h1 fp16 tiled (32MB), rb stride 65536B
__device__ __half g_p1[(size_t)MROWS * C1];       // points1 fp16 tiled (16MB), rb stride 32768B
__device__ __half g_p2[SROWS * C2];               // points2 fp16 tiled (4MB),  rb stride 65536B
__device__ int4   g_idx[MROWS];                   // 3-NN indices (GLOBAL: b*SS+s)
__device__ float4 g_wt[MROWS];                    // 3-NN weights (normalized)
// weights fp16, tiled+swizzled: [chunk][n 256 rows][64 k, SW128]
__device__ __half g_w1a[HH * C1];
__device__ __half g_w1b[HH * C2];
__device__ __half g_w2[HH * HH];
__device__ float g_s1[HH], g_b1[HH], g_s2[HH], g_b2[HH];

// ---------------------------------------------------------------------------
// Helpers
// ---------------------------------------------------------------------------
__device__ __forceinline__ uint32_t smem_u32(const void* p) {
    uint32_t a;
    asm("{ .reg .u64 t; cvta.to.shared.u64 t, %1; cvt.u32.u64 %0, t; }" : "=r"(a) : "l"(p));
    return a;
}
__device__ __forceinline__ void ldm4(uint32_t* r, uint32_t addr) {
    asm volatile("ldmatrix.sync.aligned.m8n8.x4.shared.b16 {%0,%1,%2,%3}, [%4];"
                 : "=r"(r[0]), "=r"(r[1]), "=r"(r[2]), "=r"(r[3]) : "r"(addr));
}
__device__ __forceinline__ void mma16816(float* c, const uint32_t* a, const uint32_t* b) {
    asm volatile(
        "mma.sync.aligned.m16n8k16.row.col.f32.f16.f16.f32 "
        "{%0,%1,%2,%3}, {%4,%5,%6,%7}, {%8,%9}, {%0,%1,%2,%3};"
        : "+f"(c[0]), "+f"(c[1]), "+f"(c[2]), "+f"(c[3])
        : "r"(a[0]), "r"(a[1]), "r"(a[2]), "r"(a[3]), "r"(b[0]), "r"(b[1]));
}
__device__ __forceinline__ void cp16(uint32_t dst, const void* src) {
    asm volatile("cp.async.cg.shared.global [%0], [%1], 16;" :: "r"(dst), "l"(src));
}
#define CP_COMMIT() asm volatile("cp.async.commit_group;" ::: "memory")
#define CP_WAIT()   asm volatile("cp.async.wait_group 0;" ::: "memory")

__device__ __forceinline__ uint32_t packh2(float a, float b) {
    __half2 h = __floats2half2_rn(a, b);
    return *(uint32_t*)&h;
}

// ---------------------------------------------------------------------------
// BN fold
// ---------------------------------------------------------------------------
__global__ void bn_prep(const float* __restrict__ g1, const float* __restrict__ be1,
                        const float* __restrict__ rm1, const float* __restrict__ rv1,
                        const float* __restrict__ g2, const float* __restrict__ be2,
                        const float* __restrict__ rm2, const float* __restrict__ rv2) {
    int h = threadIdx.x;
    float s1 = g1[h] * rsqrtf(rv1[h] + 1e-5f);
    g_s1[h] = s1; g_b1[h] = be1[h] - rm1[h] * s1;
    float s2 = g2[h] * rsqrtf(rv2[h] + 1e-5f);
    g_s2[h] = s2; g_b2[h] = be2[h] - rm2[h] * s2;
}

// ---------------------------------------------------------------------------
// Weight conversion into tiled+swizzled fp16
// ---------------------------------------------------------------------------
__global__ __launch_bounds__(256) void conv_weights(const float* __restrict__ W1,
                                                    const float* __restrict__ W2) {
    int i = blockIdx.x * 256 + threadIdx.x;   // 163840 total
    float v; __half* H; int n, k;
    if (i < 32768)       { n = i >> 7; k = i & 127; v = W1[n * 384 + k];             H = g_w1a; }
    else if (i < 98304)  { int j = i - 32768; n = j >> 8; k = j & 255; v = W1[n * 384 + 128 + k]; H = g_w1b; }
    else                 { int j = i - 98304; n = j >> 8; k = j & 255; v = W2[n * 256 + k];       H = g_w2; }
    int chunk = k >> 6, kin = k & 63;
    int boff = n * 128 + ((kin * 2) ^ ((n & 7) << 4));
    H[chunk * 16384 + (boff >> 1)] = __float2half_rn(v);
}

// ---------------------------------------------------------------------------
// Activation conversion: points1/points2 fp32 -> fp16 tiled+swizzled
// ---------------------------------------------------------------------------
#define P1SEGS (MROWS * (C1 / 8))    // 1048576
#define P2SEGS (SROWS * (C2 / 8))    // 262144

__global__ __launch_bounds__(256) void conv_points(const float* __restrict__ p1,
                                                   const float* __restrict__ p2) {
    int i = blockIdx.x * 256 + threadIdx.x;
    const float* src; char* dst; int r, s, KKr; size_t rbs;
    if (i < P1SEGS) { r = i >> 4; s = i & 15; src = p1; dst = (char*)g_p1; KKr = C1; rbs = 32768; }
    else {
        int j = i - P1SEGS;
        if (j >= P2SEGS) return;
        r = j >> 5; s = j & 31; src = p2; dst = (char*)g_p2; KKr = C2; rbs = 65536;
    }
    const int k0 = s * 8;
    const float* ap = src + (size_t)r * KKr + k0;
    float4 a0 = *(const float4*)(ap + 0);
    float4 a1 = *(const float4*)(ap + 4);
    uint4 h = make_uint4(packh2(a0.x, a0.y), packh2(a0.z, a0.w),
                         packh2(a1.x, a1.y), packh2(a1.z, a1.w));
    const int rb = r >> 7, rl = r & 127, chunk = k0 >> 6, kin = k0 & 63;
    const size_t off = (size_t)rb * rbs + chunk * 16384
                     + rl * 128 + (((uint32_t)kin * 2) ^ (((uint32_t)rl & 7) << 4));
    *(uint4*)(dst + off) = h;
}

// ---------------------------------------------------------------------------
// 3-NN search, 8-way partitioned scan + shfl butterfly merge.
// Block: 256 threads = 32 groups x 8 lanes; each thread handles 2 queries
// (shared candidate loads). Block covers 64 queries; grid (BB, NQ/64).
// Writes GLOBAL idx (b*SS+s) + normalized weights.
// ---------------------------------------------------------------------------
// insert (e,j) into top-3 (d0<=d1<=d2), tie-break on smaller index
#define INS3(e, jj, d0, i0, d1, i1, d2, i2) do {                               \
    if ((e) < (d2) || ((e) == (d2) && (jj) < (i2))) {                          \
        if ((e) < (d1) || ((e) == (d1) && (jj) < (i1))) {                      \
            d2 = d1; i2 = i1;                                                  \
            if ((e) < (d0) || ((e) == (d0) && (jj) < (i0))) {                  \
                d1 = d0; i1 = i0; d0 = (e); i0 = (jj);                         \
            } else { d1 = (e); i1 = (jj); }                                    \
        } else { d2 = (e); i2 = (jj); }                                        \
    }                                                                          \
} while (0)

__global__ __launch_bounds__(256) void nn_idx(const float* __restrict__ xyz1,
                                              const float* __restrict__ xyz2) {
    __shared__ __align__(16) float4 cand[SS];
    const int b = blockIdx.x, tid = threadIdx.x;
    const float* x2 = xyz2 + (size_t)b * SS * 3;
    for (int s = tid; s < SS; s += 256) {
        float x = x2[s * 3 + 0], y = x2[s * 3 + 1], z = x2[s * 3 + 2];
        cand[s] = make_float4(x, y, z, x * x + y * y + z * z);
    }
    __syncthreads();

    const int part = tid & 7;                 // scan partition
    const int qg   = tid >> 3;                // query pair group 0..31
    const int q0   = blockIdx.y * 64 + qg * 2;

    const float* qp = xyz1 + ((size_t)b * NQ + q0) * 3;
    const float ax = qp[0], ay = qp[1], az = qp[2];
    const float bx = qp[3], by = qp[4], bz = qp[5];
    const float mxa = -2.f * ax, mya = -2.f * ay, mza = -2.f * az;
    const float mxb = -2.f * bx, myb = -2.f * by, mzb = -2.f * bz;

    float da0 = 3.4e38f, da1 = 3.4e38f, da2 = 3.4e38f;
    float db0 = 3.4e38f, db1 = 3.4e38f, db2 = 3.4e38f;
    int ia0 = 0, ia1 = 0, ia2 = 0, ib0 = 0, ib1 = 0, ib2 = 0;

#pragma unroll 4
    for (int s = part; s < SS; s += 8) {
        float4 c = cand[s];
        float da = fmaf(mxa, c.x, fmaf(mya, c.y, fmaf(mza, c.z, c.w)));
        float db = fmaf(mxb, c.x, fmaf(myb, c.y, fmaf(mzb, c.z, c.w)));
        if (da < da2) {
            if (da < da1) {
                da2 = da1; ia2 = ia1;
                if (da < da0) { da1 = da0; ia1 = ia0; da0 = da; ia0 = s; }
                else          { da1 = da;  ia1 = s; }
            } else { da2 = da; ia2 = s; }
        }
        if (db < db2) {
            if (db < db1) {
                db2 = db1; ib2 = ib1;
                if (db < db0) { db1 = db0; ib1 = ib0; db0 = db; ib0 = s; }
                else          { db1 = db;  ib1 = s; }
            } else { db2 = db; ib2 = s; }
        }
    }

    // butterfly merge over the 8 partitions (groups aligned within warp)
#pragma unroll
    for (int off = 1; off < 8; off <<= 1) {
        float e0 = __shfl_xor_sync(0xFFFFFFFFu, da0, off);
        float e1 = __shfl_xor_sync(0xFFFFFFFFu, da1, off);
        float e2 = __shfl_xor_sync(0xFFFFFFFFu, da2, off);
        int   j0 = __shfl_xor_sync(0xFFFFFFFFu, ia0, off);
        int   j1 = __shfl_xor_sync(0xFFFFFFFFu, ia1, off);
        int   j2 = __shfl_xor_sync(0xFFFFFFFFu, ia2, off);
        INS3(e0, j0, da0, ia0, da1, ia1, da2, ia2);
        INS3(e1, j1, da0, ia0, da1, ia1, da2, ia2);
        INS3(e2, j2, da0, ia0, da1, ia1, da2, ia2);
        e0 = __shfl_xor_sync(0xFFFFFFFFu, db0, off);
        e1 = __shfl_xor_sync(0xFFFFFFFFu, db1, off);
        e2 = __shfl_xor_sync(0xFFFFFFFFu, db2, off);
        j0 = __shfl_xor_sync(0xFFFFFFFFu, ib0, off);
        j1 = __shfl_xor_sync(0xFFFFFFFFu, ib1, off);
        j2 = __shfl_xor_sync(0xFFFFFFFFu, ib2, off);
        INS3(e0, j0, db0, ib0, db1, ib1, db2, ib2);
        INS3(e1, j1, db0, ib0, db1, ib1, db2, ib2);
        INS3(e2, j2, db0, ib0, db1, ib1, db2, ib2);
    }

    if (part == 0) {
        const int gbase = b * SS;
        {
            const float q2 = ax * ax + ay * ay + az * az;
            float t0 = sqrtf(fmaxf(da0 + q2, 0.f));
            float t1 = sqrtf(fmaxf(da1 + q2, 0.f));
            float t2 = sqrtf(fmaxf(da2 + q2, 0.f));
            float w0 = 1.f / fmaxf(t0, 1e-10f);
            float w1 = 1.f / fmaxf(t1, 1e-10f);
            float w2 = 1.f / fmaxf(t2, 1e-10f);
            float inv = 1.f / (w0 + w1 + w2);
            g_idx[(size_t)b * NQ + q0] = make_int4(gbase + ia0, gbase + ia1, gbase + ia2, 0);
            g_wt[(size_t)b * NQ + q0]  = make_float4(w0 * inv, w1 * inv, w2 * inv, 0.f);
        }
        {
            const float q2 = bx * bx + by * by + bz * bz;
            float t0 = sqrtf(fmaxf(db0 + q2, 0.f));
            float t1 = sqrtf(fmaxf(db1 + q2, 0.f));
            float t2 = sqrtf(fmaxf(db2 + q2, 0.f));
            float w0 = 1.f / fmaxf(t0, 1e-10f);
            float w1 = 1.f / fmaxf(t1, 1e-10f);
            float w2 = 1.f / fmaxf(t2, 1e-10f);
            g_idx[(size_t)b * NQ + q0 + 1] = make_int4(gbase + ib0, gbase + ib1, gbase + ib2, 0);
            float inv = 1.f / (w0 + w1 + w2);
            g_wt[(size_t)b * NQ + q0 + 1]  = make_float4(w0 * inv, w1 * inv, w2 * inv, 0.f);
        }
    }
}

// ---------------------------------------------------------------------------
// Pipelined HMMA GEMM, single-pass fp16, ALL operands via cp.async from tiled
// fp16 global arrays. 512 threads = 16 warps, warp tile 32x32, 2 CTAs/SM.
// CTA tile 128(M) x 128(N), N split via grid.y=2. K-chunk 64, double-buffered.
//   MODE 0: A=g_p2 (K=256, rbs 65536), B=w1b -> g_Z fp32
//   MODE 1: A=g_p1 (K=128, rbs 32768), B=w1a, epi: gather(Z)+bn1+relu -> g_h1
//   MODE 2: A=g_h1 (K=256, rbs 65536), B=w2,  epi: bn2+relu -> out
// ---------------------------------------------------------------------------
#define ABYTES 16384
#define BBYTES 16384
#define STAGE  (ABYTES + BBYTES)   // 32KB
#define SMEM_SZ (2 * STAGE)        // 64KB

template <int MODE>
__global__ __launch_bounds__(512, 2) void mma_gemm(float* __restrict__ outp) {
    extern __shared__ char smem[];
    const uint32_t sb = smem_u32(smem);

    constexpr int KK  = (MODE == 1) ? 128 : 256;
    constexpr int NCH = KK / 64;
    constexpr size_t RBS = (MODE == 1) ? 32768 : 65536;

    const int tid = threadIdx.x, wid = tid >> 5, lane = tid & 31;
    const int row0 = blockIdx.x * 128;
    const int col0 = blockIdx.y * 128;
    const int wm = wid & 3, wn = wid >> 2;   // warp tile rows wm*32, cols wn*32

    const __half* BW = (MODE == 0) ? g_w1b : (MODE == 1) ? g_w1a : g_w2;
    const __half* AW = (MODE == 0) ? g_p2  : (MODE == 1) ? g_p1  : g_h1;

    float acc[2][4][4];
#pragma unroll
    for (int mt = 0; mt < 2; mt++)
#pragma unroll
        for (int nt = 0; nt < 4; nt++)
#pragma unroll
            for (int e = 0; e < 4; e++) acc[mt][nt][e] = 0.f;

    // ldmatrix per-lane bases
    const int j = lane >> 3, jlo = j & 1, jhi = j >> 1;
    const uint32_t xr = (uint32_t)(lane & 7) << 4;
    const uint32_t aRow = (uint32_t)(wm * 32 + jlo * 8 + (lane & 7)) * 128u;
    const uint32_t bRow = (uint32_t)(wn * 32 + jlo * 8 + (lane & 7)) * 128u;

    // ---- loaders (pure cp.async identity copies) ----
    auto load_AB = [&](int c, int st) {
        const char* srcA = (const char*)AW + (size_t)blockIdx.x * RBS + c * 16384;
        const char* srcB = (const char*)BW + c * 32768 + col0 * 128;
        const uint32_t dA = sb + st * STAGE;
        const uint32_t dB = dA + ABYTES;
#pragma unroll
        for (int p = 0; p < 2; p++) {
            int seg = p * 512 + tid;       // 1024 segs x 16B = 16KB each
            cp16(dA + seg * 16, srcA + seg * 16);
            cp16(dB + seg * 16, srcB + seg * 16);
        }
    };

    auto compute = [&](int bufsel) {
        const uint32_t base = sb + bufsel * STAGE;
        const uint32_t sA = base, sB = base + ABYTES;
#pragma unroll
        for (int ks = 0; ks < 4; ks++) {
            const uint32_t kb = ((uint32_t)(ks * 32 + jhi * 16)) ^ xr;
            uint32_t ah[2][4], bh[4][2];
            ldm4(ah[0], sA + aRow + kb);
            ldm4(ah[1], sA + aRow + 2048u + kb);
#pragma unroll
            for (int p = 0; p < 2; p++) {
                uint32_t r[4];
                ldm4(r, sB + bRow + p * 2048u + kb);
                bh[p * 2 + 0][0] = r[0]; bh[p * 2 + 0][1] = r[2];
                bh[p * 2 + 1][0] = r[1]; bh[p * 2 + 1][1] = r[3];
            }
#pragma unroll
            for (int mt = 0; mt < 2; mt++)
#pragma unroll
                for (int nt = 0; nt < 4; nt++)
                    mma16816(acc[mt][nt], ah[mt], bh[nt]);
        }
    };

    // ---- pipelined mainloop ----
    load_AB(0, 0);
    CP_COMMIT();
    CP_WAIT();
    __syncthreads();
    for (int c = 0; c < NCH; c++) {
        const int buf = c & 1;
        if (c + 1 < NCH) {
            load_AB(c + 1, buf ^ 1);
            CP_COMMIT();
        }
        compute(buf);
        if (c + 1 < NCH) CP_WAIT();
        __syncthreads();
    }

    // ---- epilogue ----
    const int g = lane >> 2, t = lane & 3;
    if (MODE == 0) {
#pragma unroll
        for (int mt = 0; mt < 2; mt++) {
            const int ra = row0 + wm * 32 + mt * 16 + g, rb = ra + 8;
#pragma unroll
            for (int nt = 0; nt < 4; nt++) {
                const int col = col0 + wn * 32 + nt * 8 + 2 * t;
                *(float2*)(g_Z + (size_t)ra * HH + col) = make_float2(acc[mt][nt][0], acc[mt][nt][1]);
                *(float2*)(g_Z + (size_t)rb * HH + col) = make_float2(acc[mt][nt][2], acc[mt][nt][3]);
            }
        }
    } else if (MODE == 2) {
#pragma unroll
        for (int mt = 0; mt < 2; mt++) {
            const int ra = row0 + wm * 32 + mt * 16 + g, rb = ra + 8;
#pragma unroll
            for (int nt = 0; nt < 4; nt++) {
                const int col = col0 + wn * 32 + nt * 8 + 2 * t;
                float sc0 = g_s2[col], sc1 = g_s2[col + 1];
                float bb0 = g_b2[col], bb1 = g_b2[col + 1];
                float v0 = fmaxf(fmaf(acc[mt][nt][0], sc0, bb0), 0.f);
                float v1 = fmaxf(fmaf(acc[mt][nt][1], sc1, bb1), 0.f);
                float v2 = fmaxf(fmaf(acc[mt][nt][2], sc0, bb0), 0.f);
                float v3 = fmaxf(fmaf(acc[mt][nt][3], sc1, bb1), 0.f);
                *(float2*)(outp + (size_t)ra * HH + col) = make_float2(v0, v1);
                *(float2*)(outp + (size_t)rb * HH + col) = make_float2(v2, v3);
            }
        }
    } else {
        // MODE 1: gather from Z, bn1+relu, fp16 convert, stage (32KB), copy out
#pragma unroll
        for (int mt = 0; mt < 2; mt++) {
            const int rla = wm * 32 + mt * 16 + g, rlb = rla + 8;
            const int ra = row0 + rla, rb = row0 + rlb;
            const int4   ia = g_idx[ra], ib = g_idx[rb];
            const float4 wa = g_wt[ra],  wb = g_wt[rb];
#pragma unroll
            for (int nt = 0; nt < 4; nt++) {
                const int lcol = wn * 32 + nt * 8 + 2 * t;
                const int col = col0 + lcol;
                float2 za0 = *(const float2*)(g_Z + (size_t)ia.x * HH + col);
                float2 za1 = *(const float2*)(g_Z + (size_t)ia.y * HH + col);
                float2 za2 = *(const float2*)(g_Z + (size_t)ia.z * HH + col);
                float2 zb0 = *(const float2*)(g_Z + (size_t)ib.x * HH + col);
                float2 zb1 = *(const float2*)(g_Z + (size_t)ib.y * HH + col);
                float2 zb2 = *(const float2*)(g_Z + (size_t)ib.z * HH + col);
                float p0 = fmaf(wa.x, za0.x, fmaf(wa.y, za1.x, wa.z * za2.x));
                float p1 = fmaf(wa.x, za0.y, fmaf(wa.y, za1.y, wa.z * za2.y));
                float p2 = fmaf(wb.x, zb0.x, fmaf(wb.y, zb1.x, wb.z * zb2.x));
                float p3 = fmaf(wb.x, zb0.y, fmaf(wb.y, zb1.y, wb.z * zb2.y));
                float sc0 = g_s1[col], sc1 = g_s1[col + 1];
                float bb0 = g_b1[col], bb1 = g_b1[col + 1];
                float v0 = fmaxf(fmaf(acc[mt][nt][0] + p0, sc0, bb0), 0.f);
                float v1 = fmaxf(fmaf(acc[mt][nt][1] + p1, sc1, bb1), 0.f);
                float v2 = fmaxf(fmaf(acc[mt][nt][2] + p2, sc0, bb0), 0.f);
                float v3 = fmaxf(fmaf(acc[mt][nt][3] + p3, sc1, bb1), 0.f);
                const int lc = lcol >> 6, kin = lcol & 63;
                const uint32_t offa = lc * 16384 + (uint32_t)rla * 128 + (((uint32_t)kin * 2) ^ (((uint32_t)rla & 7) << 4));
                const uint32_t offb = lc * 16384 + (uint32_t)rlb * 128 + (((uint32_t)kin * 2) ^ (((uint32_t)rlb & 7) << 4));
                *(uint32_t*)(smem + offa) = packh2(v0, v1);
                *(uint32_t*)(smem + offb) = packh2(v2, v3);
            }
        }
        __syncthreads();
        // coalesced copy of staged 2 chunks (32KB) to global tiled layout
        // h1 row-block stride = 65536 B; grid.y selects chunks {0,1} or {2,3}
        char* dst = (char*)g_h1 + (size_t)blockIdx.x * 65536 + (size_t)blockIdx.y * 32768;
#pragma unroll
        for (int p = 0; p < 4; p++) {
            int seg = p * 512 + tid;     // 2048 segs x 16B = 32KB
            *(uint4*)(dst + seg * 16) = *(const uint4*)(smem + seg * 16);
        }
    }
}

// ---------------------------------------------------------------------------
// Launch
// ---------------------------------------------------------------------------
extern "C" void kernel_launch(void* const* d_in, const int* in_sizes, int n_in,
                              void* d_out, int out_size) {
    const float* xyz1    = (const float*)d_in[0];
    const float* xyz2    = (const float*)d_in[1];
    const float* points1 = (const float*)d_in[2];
    const float* points2 = (const float*)d_in[3];
    const float* W1      = (const float*)d_in[4];
    const float* gamma1  = (const float*)d_in[5];
    const float* beta1   = (const float*)d_in[6];
    const float* rm1     = (const float*)d_in[7];
    const float* rv1     = (const float*)d_in[8];
    const float* W2      = (const float*)d_in[9];
    const float* gamma2  = (const float*)d_in[10];
    const float* beta2   = (const float*)d_in[11];
    const float* rm2     = (const float*)d_in[12];
    const float* rv2     = (const float*)d_in[13];
    float* out = (float*)d_out;

    cudaFuncSetAttribute(mma_gemm<0>, cudaFuncAttributeMaxDynamicSharedMemorySize, SMEM_SZ);
    cudaFuncSetAttribute(mma_gemm<1>, cudaFuncAttributeMaxDynamicSharedMemorySize, SMEM_SZ);
    cudaFuncSetAttribute(mma_gemm<2>, cudaFuncAttributeMaxDynamicSharedMemorySize, SMEM_SZ);

    bn_prep<<<1, HH>>>(gamma1, beta1, rm1, rv1, gamma2, beta2, rm2, rv2);
    conv_weights<<<640, 256>>>(W1, W2);
    conv_points<<<(P1SEGS + P2SEGS + 255) / 256, 256>>>(points1, points2);

    // 3-NN indices + weights (global indices); 64 queries per block
    nn_idx<<<dim3(BB, NQ / 64), 256>>>(xyz1, xyz2);

    // Z = points2 @ W1b^T
    mma_gemm<0><<<dim3(SROWS / 128, 2), 512, SMEM_SZ>>>(nullptr);

    // h1 = relu(bn1(points1 @ W1a^T + gather(Z)))  -> g_h1 fp16 tiled
    mma_gemm<1><<<dim3(MROWS / 128, 2), 512, SMEM_SZ>>>(nullptr);

    // out = relu(bn2(h1 @ W2^T))
    mma_gemm<2><<<dim3(MROWS / 128, 2), 512, SMEM_SZ>>>(out);
}